// round 13
// baseline (speedup 1.0000x reference)
#include <cuda_runtime.h>
#include <cuda_fp16.h>
#include <cstdint>

#define NPTS 8192
#define KN   32
#define DIM  256
#define DOUT 512
#define NTILES 4096      // m64 tiles over M = NPTS*KN = 262144
#define NQTILES 128
#define GRID1 152
#define PE_BLOCKS 304
#define CVT_BLOCKS 152
#define PREP_GRID (PE_BLOCKS + CVT_BLOCKS)

// ---------------- device scratch (allocation-free rule) ----------------
__device__ float  g_qattn[NPTS * DIM];
__device__ __half g_fq16[NPTS * DIM];
__device__ __half g_res16[NPTS * DIM];
__device__ __half g_bufA[(size_t)NPTS * KN * DIM];  // F16, later A1
__device__ __half g_pe  [(size_t)NPTS * KN * DIM];
__device__ __half g_h   [(size_t)NPTS * KN * DIM];
__device__ __half g_vpe [(size_t)NPTS * KN * DIM];
__device__ __half g_WkB[DIM * DIM];   // -Wk, blocked
__device__ __half g_WvB[DIM * DIM];
__device__ __half g_g1B[DIM * DIM];
__device__ __half g_g2B[DIM * DIM];
__device__ __half g_d2B[DIM * 128];
__device__ __half g_WqB[DIM * DIM];
__device__ __half g_owB[DIM * DOUT];

__device__ __forceinline__ int boff(int n, int k) {
    return ((k >> 4) * 8192 + (n >> 3) * 256 + ((k >> 3) & 1) * 128 +
            (n & 7) * 16 + (k & 7) * 2) >> 1;
}
__device__ __forceinline__ int boff512(int n, int k) {
    return ((k >> 4) * 16384 + (n >> 3) * 256 + ((k >> 3) & 1) * 128 +
            (n & 7) * 16 + (k & 7) * 2) >> 1;
}

extern "C" __global__ void convert_all(const float* __restrict__ Wk,
                                       const float* __restrict__ Wv,
                                       const float* __restrict__ g1w,
                                       const float* __restrict__ g2w,
                                       const float* __restrict__ d2w,
                                       const float* __restrict__ Wq,
                                       const float* __restrict__ ow) {
    int idx = blockIdx.x * 256 + threadIdx.x;
    if (idx < 65536) {
        int k = idx >> 8, n = idx & 255;
        g_WkB[boff(n, k)] = __float2half(-Wk[k * 256 + n]);
    } else if (idx < 131072) {
        int i = idx - 65536; int k = i >> 8, n = i & 255;
        g_WvB[boff(n, k)] = __float2half(Wv[k * 256 + n]);
    } else if (idx < 196608) {
        int i = idx - 131072; int k = i >> 8, n = i & 255;
        g_g1B[boff(n, k)] = __float2half(g1w[k * 256 + n]);
    } else if (idx < 262144) {
        int i = idx - 196608; int k = i >> 8, n = i & 255;
        g_g2B[boff(n, k)] = __float2half(g2w[k * 256 + n]);
    } else if (idx < 294912) {
        int i = idx - 262144; int k = i >> 8, n = i & 255;
        g_d2B[boff(n, k)] = __float2half(d2w[k * 256 + n]);
    } else if (idx < 360448) {
        int i = idx - 294912; int k = i >> 8, n = i & 255;
        g_WqB[boff(n, k)] = __float2half(Wq[k * 256 + n]);
    } else if (idx < 491520) {
        int i = idx - 360448; int k = i >> 9, n = i & 511;
        g_owB[boff512(n, k)] = __float2half(ow[k * 512 + n]);
    }
}

extern "C" __global__ void copy_xyz_kernel(const float* __restrict__ src,
                                           float* __restrict__ dst, int n) {
    int i = blockIdx.x * blockDim.x + threadIdx.x;
    if (i < n) dst[i] = src[i];
}

// =======================================================================
__device__ __forceinline__ unsigned int swz(unsigned int row, unsigned int cb,
                                            unsigned int rb) {
    return row * rb + (cb ^ ((row & 7u) << 4));
}
__device__ __forceinline__ void cp_async16(unsigned int dst, const void* src) {
    asm volatile("cp.async.cg.shared.global [%0], [%1], 16;\n" :: "r"(dst), "l"(src) : "memory");
}
#define CP_COMMIT() asm volatile("cp.async.commit_group;\n" ::: "memory")
#define CP_WAIT(n)  asm volatile("cp.async.wait_group %0;\n" :: "n"(n) : "memory")

__device__ __forceinline__ void stage_tile(unsigned int dstb,
                                           const __half* __restrict__ src,
                                           size_t row0, int tid) {
#pragma unroll
    for (int i = 0; i < 4; ++i) {
        int c = tid + i * 512;
        unsigned int row = (unsigned int)(c >> 5);
        unsigned int c16 = (unsigned int)(c & 31) * 16u;
        cp_async16(dstb + swz(row, c16, 512u),
                   (const char*)(src + (row0 + row) * 256) + c16);
    }
}

template <int NSTEPS>
__device__ __forceinline__ void compute_tile(float (&acc)[2][4][4],
                                             unsigned int Abase, unsigned int arb,
                                             unsigned int Wbase, unsigned int kss,
                                             int lane, int wm, int wnl) {
    const int lr  = (lane & 7) + ((lane >> 3) & 1) * 8;
    const int lcb = ((lane >> 4) & 1) * 16;
    const int ntp = (lane >> 4) & 1;
    const int kh  = (lane >> 3) & 1;
    const int rr  = lane & 7;
#pragma unroll 4
    for (int ks = 0; ks < NSTEPS; ++ks) {
        unsigned int bf[2][4];
#pragma unroll
        for (int bg = 0; bg < 2; ++bg) {
            unsigned int ba = Wbase + (unsigned int)ks * kss
                            + (unsigned int)((wnl * 4 + bg * 2 + ntp) * 256 + kh * 128 + rr * 16);
            asm volatile("ldmatrix.sync.aligned.m8n8.x4.shared.b16 {%0,%1,%2,%3}, [%4];\n"
                         : "=r"(bf[bg][0]), "=r"(bf[bg][1]), "=r"(bf[bg][2]), "=r"(bf[bg][3])
                         : "r"(ba));
        }
#pragma unroll
        for (int mt = 0; mt < 2; ++mt) {
            unsigned int a0, a1, a2, a3;
            unsigned int ad = Abase + swz((unsigned int)(wm * 32 + mt * 16 + lr),
                                          (unsigned int)(ks * 32 + lcb), arb);
            asm volatile("ldmatrix.sync.aligned.m8n8.x4.shared.b16 {%0,%1,%2,%3}, [%4];\n"
                         : "=r"(a0), "=r"(a1), "=r"(a2), "=r"(a3) : "r"(ad));
#pragma unroll
            for (int nt = 0; nt < 4; ++nt) {
                asm volatile(
                    "mma.sync.aligned.m16n8k16.row.col.f32.f16.f16.f32 "
                    "{%0,%1,%2,%3},{%4,%5,%6,%7},{%8,%9},{%0,%1,%2,%3};\n"
                    : "+f"(acc[mt][nt][0]), "+f"(acc[mt][nt][1]),
                      "+f"(acc[mt][nt][2]), "+f"(acc[mt][nt][3])
                    : "r"(a0), "r"(a1), "r"(a2), "r"(a3),
                      "r"(bf[nt >> 1][(nt & 1) * 2]), "r"(bf[nt >> 1][(nt & 1) * 2 + 1]));
            }
        }
    }
}

#define ZERO_ACC(acc) \
    _Pragma("unroll") for (int _m = 0; _m < 2; ++_m) { \
    _Pragma("unroll") for (int _n = 0; _n < 4; ++_n) { \
    _Pragma("unroll") for (int _i = 0; _i < 4; ++_i) { acc[_m][_n][_i] = 0.f; } } }

// =======================================================================
// prep kernel: heterogeneous grid.
//   blocks [0, 304): pe = H1@d2 per point (d2 resident in smem)
//   blocks [304, 456): grid-stride fp32->fp16 convert of feats_kv / feats_q
// 456 CTAs x 256 thr x 72KB smem = exactly 3 CTAs/SM, one wave.
// =======================================================================
extern "C" __global__ void __launch_bounds__(256, 3)
prep_kernel(const float* __restrict__ xyz_q, const float* __restrict__ xyz_kv,
            const float* __restrict__ d1w, const float* __restrict__ d1b,
            const float* __restrict__ feats_kv, const float* __restrict__ feats_q) {
    const int bid = blockIdx.x;
    const int tid = threadIdx.x;

    if (bid >= PE_BLOCKS) {
        // ---------------- converter blocks (no smem use) ----------------
        const int cid = bid - PE_BLOCKS;
        const size_t KV8 = (size_t)NPTS * KN * DIM / 8;   // 8388608
        const size_t Q8  = (size_t)NPTS * DIM / 8;        // 262144
        const size_t stride = (size_t)CVT_BLOCKS * 256;
        for (size_t idx = (size_t)cid * 256 + tid; idx < KV8 + Q8; idx += stride) {
            const float4* src; __half* dst; size_t e;
            if (idx < KV8) { src = (const float4*)feats_kv; dst = g_bufA; e = idx * 2; }
            else           { src = (const float4*)feats_q;  dst = g_fq16; e = (idx - KV8) * 2; }
            float4 a = __ldg(src + e), b = __ldg(src + e + 1);
            __half2 h0 = __floats2half2_rn(a.x, a.y), h1 = __floats2half2_rn(a.z, a.w);
            __half2 h2 = __floats2half2_rn(b.x, b.y), h3 = __floats2half2_rn(b.z, b.w);
            uint4 u = make_uint4(*(unsigned int*)&h0, *(unsigned int*)&h1,
                                 *(unsigned int*)&h2, *(unsigned int*)&h3);
            *(uint4*)(dst + e * 4) = u;
        }
        return;
    }

    // ---------------- pe blocks ----------------
    extern __shared__ char smem[];
    const unsigned int smb = (unsigned int)__cvta_generic_to_shared(smem);
    const int lane = tid & 31;
    const int wnl  = tid >> 5;
    const int g    = lane >> 2, tig = lane & 3;

    for (int i = tid; i < 4096; i += 256) {
        cp_async16(smb + (unsigned int)(i * 16), (const char*)g_d2B + i * 16);
    }
    CP_COMMIT(); CP_WAIT(0);
    __syncthreads();

    const unsigned int H1 = smb + 65536u;
    for (int pt = bid; pt < NPTS; pt += PE_BLOCKS) {
        __syncthreads();
        {
            unsigned int row = (unsigned int)(tid >> 3);
            int cb = (tid & 7) * 16;
            float qx = __ldg(xyz_q + pt * 3 + 0);
            float qy = __ldg(xyz_q + pt * 3 + 1);
            float qz = __ldg(xyz_q + pt * 3 + 2);
            const float* pk = xyz_kv + ((size_t)pt * KN + row) * 3;
            float rx = qx - __ldg(pk + 0), ry = qy - __ldg(pk + 1), rz = qz - __ldg(pk + 2);
#pragma unroll 4
            for (int c = cb; c < cb + 16; c += 2) {
                float h0 = fmaf(rx, __ldg(d1w + c),     fmaf(ry, __ldg(d1w + 128 + c),     fmaf(rz, __ldg(d1w + 256 + c),     __ldg(d1b + c))));
                float h1 = fmaf(rx, __ldg(d1w + c + 1), fmaf(ry, __ldg(d1w + 128 + c + 1), fmaf(rz, __ldg(d1w + 256 + c + 1), __ldg(d1b + c + 1))));
                __half2 hh = __floats2half2_rn(fmaxf(h0, 0.f), fmaxf(h1, 0.f));
                *(__half2*)(smem + 65536 + swz(row, (unsigned int)c * 2u, 256u)) = hh;
            }
        }
        __syncthreads();
        float acc[2][4][4];
        ZERO_ACC(acc);
        compute_tile<8>(acc, H1, 256u, smb, 8192u, lane, 0, wnl);
#pragma unroll
        for (int nt = 0; nt < 4; ++nt) {
            int c = wnl * 32 + nt * 8 + 2 * tig;
#pragma unroll
            for (int mt = 0; mt < 2; ++mt) {
                size_t r0 = (size_t)pt * 32 + mt * 16 + g;
                __half2 lo = __floats2half2_rn(acc[mt][nt][0], acc[mt][nt][1]);
                __half2 hi = __floats2half2_rn(acc[mt][nt][2], acc[mt][nt][3]);
                *(__half2*)(g_pe + r0 * 256 + c)       = lo;
                *(__half2*)(g_pe + (r0 + 8) * 256 + c) = hi;
            }
        }
    }
}

// =======================================================================
extern "C" __global__ void __launch_bounds__(512, 1)
qproj_mma() {
    extern __shared__ char smem[];
    const unsigned int smb = (unsigned int)__cvta_generic_to_shared(smem);
    const int tid  = threadIdx.x;
    const int lane = tid & 31;
    const int wid  = tid >> 5;
    const int wm   = (wid >> 3) & 1, wnl = wid & 7;
    const int g    = lane >> 2, tig = lane & 3;
    const int t    = blockIdx.x;

    for (int i = tid; i < 8192; i += 512) {
        cp_async16(smb + (unsigned int)(i * 16), (const char*)g_WqB + i * 16);
    }
    stage_tile(smb + 131072u, g_fq16, (size_t)t * 64, tid);
    CP_COMMIT(); CP_WAIT(0);
    __syncthreads();

    float acc[2][4][4];
    ZERO_ACC(acc);
    compute_tile<16>(acc, smb + 131072u, 512u, smb, 8192u, lane, wm, wnl);
#pragma unroll
    for (int nt = 0; nt < 4; ++nt) {
        int c = wnl * 32 + nt * 8 + 2 * tig;
#pragma unroll
        for (int mt = 0; mt < 2; ++mt) {
            size_t r0 = (size_t)t * 64 + wm * 32 + mt * 16 + g;
            g_qattn[r0 * 256 + c]           = acc[mt][nt][0];
            g_qattn[r0 * 256 + c + 1]       = acc[mt][nt][1];
            g_qattn[(r0 + 8) * 256 + c]     = acc[mt][nt][2];
            g_qattn[(r0 + 8) * 256 + c + 1] = acc[mt][nt][3];
        }
    }
}

extern "C" __global__ void __launch_bounds__(512, 1)
outproj_mma(const float* __restrict__ ob, float* __restrict__ out, long long ofs) {
    extern __shared__ char smem[];
    const unsigned int smb = (unsigned int)__cvta_generic_to_shared(smem);
    const int tid  = threadIdx.x;
    const int lane = tid & 31;
    const int wid  = tid >> 5;
    const int wm   = (wid >> 3) & 1, wnl = wid & 7;
    const int g    = lane >> 2, tig = lane & 3;
    const int t    = blockIdx.x >> 1;
    const int nh   = blockIdx.x & 1;

    for (int i = tid; i < 8192; i += 512) {
        int kb = i >> 9, rem = i & 511;
        cp_async16(smb + (unsigned int)(kb * 8192 + rem * 16),
                   (const char*)g_owB + kb * 16384 + nh * 8192 + rem * 16);
    }
    stage_tile(smb + 131072u, g_res16, (size_t)t * 64, tid);
    CP_COMMIT(); CP_WAIT(0);
    __syncthreads();

    float acc[2][4][4];
    ZERO_ACC(acc);
    compute_tile<16>(acc, smb + 131072u, 512u, smb, 8192u, lane, wm, wnl);
    float* dst = out + ofs;
#pragma unroll
    for (int nt = 0; nt < 4; ++nt) {
        int c = nh * 256 + wnl * 32 + nt * 8 + 2 * tig;
        float b0 = __ldg(ob + c), b1 = __ldg(ob + c + 1);
#pragma unroll
        for (int mt = 0; mt < 2; ++mt) {
            size_t r0 = (size_t)t * 64 + wm * 32 + mt * 16 + g;
            dst[r0 * 512 + c]           = acc[mt][nt][0] + b0;
            dst[r0 * 512 + c + 1]       = acc[mt][nt][1] + b1;
            dst[(r0 + 8) * 512 + c]     = acc[mt][nt][2] + b0;
            dst[(r0 + 8) * 512 + c + 1] = acc[mt][nt][3] + b1;
        }
    }
}

// =======================================================================
// AB: h = q + d2b + pe + F@(-Wk) ; vpe = d2b + pe + F@Wv
// =======================================================================
extern "C" __global__ void __launch_bounds__(512, 1)
pass_ab(const float* __restrict__ d2b) {
    extern __shared__ char smem[];
    const unsigned int smb = (unsigned int)__cvta_generic_to_shared(smem);
    const int tid  = threadIdx.x;
    const int lane = tid & 31;
    const int wid  = tid >> 5;
    const int b    = blockIdx.x;
    const int nh   = b & 1;
    const int out  = wid >> 3;
    const int w8   = wid & 7;
    const int wm   = w8 >> 2, wnl = w8 & 3;
    const int g    = lane >> 2, tig = lane & 3;
    const unsigned int Wbase = smb + (unsigned int)out * 65536u;
    const unsigned int DB = smb + 131072u;

    for (int i = tid; i < 8192; i += 512) {
        int w = i >> 12, c = i & 4095, ks = c >> 8, rem = c & 255;
        const char* srcb = (const char*)(w ? g_WvB : g_WkB) + ks * 8192 + nh * 4096 + rem * 16;
        cp_async16(smb + (unsigned int)(w * 65536 + ks * 4096 + rem * 16), srcb);
    }
    const int t0 = b >> 1;
    stage_tile(DB, g_bufA, (size_t)t0 * 64, tid);
    CP_COMMIT();
    if (t0 + GRID1 < NTILES) {
        stage_tile(DB + 32768u, g_bufA, (size_t)(t0 + GRID1) * 64, tid);
        CP_COMMIT();
    }

    int cc[4]; float bb0[4], bb1[4];
#pragma unroll
    for (int nt = 0; nt < 4; ++nt) {
        cc[nt]  = nh * 128 + wnl * 32 + nt * 8 + 2 * tig;
        bb0[nt] = __ldg(d2b + cc[nt]);
        bb1[nt] = __ldg(d2b + cc[nt] + 1);
    }

    int it = 0;
    for (int t = t0; t < NTILES; t += GRID1, ++it) {
        if (t + GRID1 < NTILES) { CP_WAIT(1); } else { CP_WAIT(0); }
        __syncthreads();
        int t2 = t + 2 * GRID1;
        if (t2 < NTILES) {
            stage_tile(DB + (unsigned int)((it + 2) % 3) * 32768u, g_bufA, (size_t)t2 * 64, tid);
            CP_COMMIT();
        }
        unsigned int peP[4][4];
        float a0[4], a1[4];
        {
            const float* qrow = g_qattn + (size_t)(t * 2 + wm) * DIM;
            const size_t rbase = (size_t)t * 64 + wm * 32;
#pragma unroll
            for (int nt = 0; nt < 4; ++nt) {
                int c = cc[nt];
                a0[nt] = bb0[nt]; a1[nt] = bb1[nt];
                if (out == 0) { a0[nt] += __ldg(qrow + c); a1[nt] += __ldg(qrow + c + 1); }
#pragma unroll
                for (int mt = 0; mt < 2; ++mt) {
                    size_t r0 = rbase + mt * 16 + g;
                    peP[nt][mt * 2]     = __ldg((const unsigned int*)(g_pe + r0 * 256 + c));
                    peP[nt][mt * 2 + 1] = __ldg((const unsigned int*)(g_pe + (r0 + 8) * 256 + c));
                }
            }
        }

        float acc[2][4][4];
        ZERO_ACC(acc);
        compute_tile<16>(acc, DB + (unsigned int)(it % 3) * 32768u, 512u, Wbase, 4096u, lane, wm, wnl);

        __half* dstArr = out ? g_vpe : g_h;
#pragma unroll
        for (int nt = 0; nt < 4; ++nt) {
            int c = cc[nt];
#pragma unroll
            for (int mt = 0; mt < 2; ++mt) {
                size_t r0 = (size_t)t * 64 + wm * 32 + mt * 16 + g;
                float2 pl = __half22float2(*(__half2*)&peP[nt][mt * 2]);
                float2 ph = __half22float2(*(__half2*)&peP[nt][mt * 2 + 1]);
                __half2 lo = __floats2half2_rn(acc[mt][nt][0] + a0[nt] + pl.x,
                                               acc[mt][nt][1] + a1[nt] + pl.y);
                __half2 hi = __floats2half2_rn(acc[mt][nt][2] + a0[nt] + ph.x,
                                               acc[mt][nt][3] + a1[nt] + ph.y);
                *(__half2*)(dstArr + r0 * 256 + c)       = lo;
                *(__half2*)(dstArr + (r0 + 8) * 256 + c) = hi;
            }
        }
    }
}

// =======================================================================
// C: A1 = relu(h @ g1 + g1b) -> g_bufA. g1 resident. grid 152.
// =======================================================================
extern "C" __global__ void __launch_bounds__(512, 1)
pass_c(const float* __restrict__ g1b) {
    extern __shared__ char smem[];
    const unsigned int smb = (unsigned int)__cvta_generic_to_shared(smem);
    const int tid  = threadIdx.x;
    const int lane = tid & 31;
    const int wid  = tid >> 5;
    const int wm   = (wid >> 3) & 1, wnl = wid & 7;
    const int g    = lane >> 2, tig = lane & 3;
    const unsigned int DB = smb + 131072u;

    for (int i = tid; i < 8192; i += 512) {
        cp_async16(smb + (unsigned int)(i * 16), (const char*)g_g1B + i * 16);
    }
    const int t0 = blockIdx.x;
    stage_tile(DB, g_h, (size_t)t0 * 64, tid);
    CP_COMMIT();
    if (t0 + GRID1 < NTILES) {
        stage_tile(DB + 32768u, g_h, (size_t)(t0 + GRID1) * 64, tid);
        CP_COMMIT();
    }

    int cc[4]; float bb0[4], bb1[4];
#pragma unroll
    for (int nt = 0; nt < 4; ++nt) {
        cc[nt]  = wnl * 32 + nt * 8 + 2 * tig;
        bb0[nt] = __ldg(g1b + cc[nt]);
        bb1[nt] = __ldg(g1b + cc[nt] + 1);
    }

    int it = 0;
    for (int t = t0; t < NTILES; t += GRID1, ++it) {
        if (t + GRID1 < NTILES) { CP_WAIT(1); } else { CP_WAIT(0); }
        __syncthreads();
        int t2 = t + 2 * GRID1;
        if (t2 < NTILES) {
            stage_tile(DB + (unsigned int)((it + 2) % 3) * 32768u, g_h, (size_t)t2 * 64, tid);
            CP_COMMIT();
        }
        float acc[2][4][4];
        ZERO_ACC(acc);
        compute_tile<16>(acc, DB + (unsigned int)(it % 3) * 32768u, 512u, smb, 8192u, lane, wm, wnl);
#pragma unroll
        for (int nt = 0; nt < 4; ++nt) {
            int c = cc[nt];
#pragma unroll
            for (int mt = 0; mt < 2; ++mt) {
                size_t r0 = (size_t)t * 64 + wm * 32 + mt * 16 + g;
                __half2 lo = __floats2half2_rn(fmaxf(acc[mt][nt][0] + bb0[nt], 0.f),
                                               fmaxf(acc[mt][nt][1] + bb1[nt], 0.f));
                __half2 hi = __floats2half2_rn(fmaxf(acc[mt][nt][2] + bb0[nt], 0.f),
                                               fmaxf(acc[mt][nt][3] + bb1[nt], 0.f));
                *(__half2*)(g_bufA + r0 * 256 + c)       = lo;
                *(__half2*)(g_bufA + (r0 + 8) * 256 + c) = hi;
            }
        }
    }
}

// =======================================================================
// D: logits = A1 @ g2 + g2b; softmax over 32 neighbors; res -> g_res16.
// =======================================================================
extern "C" __global__ void __launch_bounds__(512, 1)
pass_d(const float* __restrict__ g2b) {
    extern __shared__ char smem[];
    const unsigned int smb = (unsigned int)__cvta_generic_to_shared(smem);
    const int tid  = threadIdx.x;
    const int lane = tid & 31;
    const int wid  = tid >> 5;
    const int wm   = (wid >> 3) & 1, wnl = wid & 7;
    const int g    = lane >> 2, tig = lane & 3;
    const unsigned int DB = smb + 131072u;

    for (int i = tid; i < 8192; i += 512) {
        cp_async16(smb + (unsigned int)(i * 16), (const char*)g_g2B + i * 16);
    }
    const int t0 = blockIdx.x;
    stage_tile(DB, g_bufA, (size_t)t0 * 64, tid);
    CP_COMMIT();
    if (t0 + GRID1 < NTILES) {
        stage_tile(DB + 32768u, g_bufA, (size_t)(t0 + GRID1) * 64, tid);
        CP_COMMIT();
    }

    int cc[4]; float bb0[4], bb1[4];
#pragma unroll
    for (int nt = 0; nt < 4; ++nt) {
        cc[nt]  = wnl * 32 + nt * 8 + 2 * tig;
        bb0[nt] = __ldg(g2b + cc[nt]);
        bb1[nt] = __ldg(g2b + cc[nt] + 1);
    }

    int it = 0;
    for (int t = t0; t < NTILES; t += GRID1, ++it) {
        if (t + GRID1 < NTILES) { CP_WAIT(1); } else { CP_WAIT(0); }
        __syncthreads();
        int t2 = t + 2 * GRID1;
        if (t2 < NTILES) {
            stage_tile(DB + (unsigned int)((it + 2) % 3) * 32768u, g_bufA, (size_t)t2 * 64, tid);
            CP_COMMIT();
        }
        unsigned int vP[4][4];
        {
            const size_t rb = (size_t)t * 64 + wm * 32;
#pragma unroll
            for (int nt = 0; nt < 4; ++nt) {
                int c = cc[nt];
                vP[nt][0] = __ldg((const unsigned int*)(g_vpe + (rb + g) * 256 + c));
                vP[nt][1] = __ldg((const unsigned int*)(g_vpe + (rb + 8 + g) * 256 + c));
                vP[nt][2] = __ldg((const unsigned int*)(g_vpe + (rb + 16 + g) * 256 + c));
                vP[nt][3] = __ldg((const unsigned int*)(g_vpe + (rb + 24 + g) * 256 + c));
            }
        }

        float acc[2][4][4];
        ZERO_ACC(acc);
        compute_tile<16>(acc, DB + (unsigned int)(it % 3) * 32768u, 512u, smb, 8192u, lane, wm, wnl);

#pragma unroll
        for (int nt = 0; nt < 4; ++nt) {
            int c = cc[nt];
            float2 v00 = __half22float2(*(__half2*)&vP[nt][0]);
            float2 v01 = __half22float2(*(__half2*)&vP[nt][1]);
            float2 v10 = __half22float2(*(__half2*)&vP[nt][2]);
            float2 v11 = __half22float2(*(__half2*)&vP[nt][3]);
#pragma unroll
            for (int ci = 0; ci < 2; ++ci) {
                float gb = ci ? bb1[nt] : bb0[nt];
                float l0 = acc[0][nt][ci]     + gb;
                float l1 = acc[0][nt][ci + 2] + gb;
                float l2 = acc[1][nt][ci]     + gb;
                float l3 = acc[1][nt][ci + 2] + gb;
                float v0 = ci ? v00.y : v00.x;
                float v1 = ci ? v01.y : v01.x;
                float v2 = ci ? v10.y : v10.x;
                float v3 = ci ? v11.y : v11.x;
                float mx = fmaxf(fmaxf(l0, l1), fmaxf(l2, l3));
                mx = fmaxf(mx, __shfl_xor_sync(0xffffffffu, mx, 4));
                mx = fmaxf(mx, __shfl_xor_sync(0xffffffffu, mx, 8));
                mx = fmaxf(mx, __shfl_xor_sync(0xffffffffu, mx, 16));
                float e0 = __expf(l0 - mx), e1 = __expf(l1 - mx);
                float e2 = __expf(l2 - mx), e3 = __expf(l3 - mx);
                float ss = (e0 + e1) + (e2 + e3);
                float ws = (e0 * v0 + e1 * v1) + (e2 * v2 + e3 * v3);
                ss += __shfl_xor_sync(0xffffffffu, ss, 4);
                ws += __shfl_xor_sync(0xffffffffu, ws, 4);
                ss += __shfl_xor_sync(0xffffffffu, ss, 8);
                ws += __shfl_xor_sync(0xffffffffu, ws, 8);
                ss += __shfl_xor_sync(0xffffffffu, ss, 16);
                ws += __shfl_xor_sync(0xffffffffu, ws, 16);
                if (g == 0) {
                    g_res16[(size_t)(t * 2 + wm) * DIM + c + ci] = __float2half(ws / ss);
                }
            }
        }
    }
}

// =======================================================================
extern "C" void kernel_launch(void* const* d_in, const int* in_sizes, int n_in,
                              void* d_out, int out_size) {
    const float* xyz_q    = (const float*)d_in[0];
    const float* feats_q  = (const float*)d_in[1];
    const float* xyz_kv   = (const float*)d_in[2];
    const float* feats_kv = (const float*)d_in[3];
    const float* Wq       = (const float*)d_in[4];
    const float* Wk       = (const float*)d_in[5];
    const float* Wv       = (const float*)d_in[6];
    const float* d1w      = (const float*)d_in[7];
    const float* d1b      = (const float*)d_in[8];
    const float* d2w      = (const float*)d_in[9];
    const float* d2b      = (const float*)d_in[10];
    const float* g1w      = (const float*)d_in[11];
    const float* g1b      = (const float*)d_in[12];
    const float* g2w      = (const float*)d_in[13];
    const float* g2b      = (const float*)d_in[14];
    const float* ow       = (const float*)d_in[15];
    const float* obias    = (const float*)d_in[16];
    float* out = (float*)d_out;

    long long ofs = (long long)out_size - (long long)NPTS * DOUT;
    if (ofs < 0) ofs = 0;
    if (ofs > 0)
        copy_xyz_kernel<<<(int)((ofs + 255) / 256), 256>>>(xyz_q, out, (int)ofs);

    convert_all<<<1920, 256>>>(Wk, Wv, g1w, g2w, d2w, Wq, ow);

    cudaFuncSetAttribute(prep_kernel, cudaFuncAttributeMaxDynamicSharedMemorySize, 73728);
    cudaFuncSetAttribute(qproj_mma,   cudaFuncAttributeMaxDynamicSharedMemorySize, 163840);
    cudaFuncSetAttribute(outproj_mma, cudaFuncAttributeMaxDynamicSharedMemorySize, 163840);
    cudaFuncSetAttribute(pass_ab, cudaFuncAttributeMaxDynamicSharedMemorySize, 229376);
    cudaFuncSetAttribute(pass_c,  cudaFuncAttributeMaxDynamicSharedMemorySize, 229376);
    cudaFuncSetAttribute(pass_d,  cudaFuncAttributeMaxDynamicSharedMemorySize, 229376);

    prep_kernel<<<PREP_GRID, 256, 73728>>>(xyz_q, xyz_kv, d1w, d1b, feats_kv, feats_q);
    qproj_mma<<<NQTILES, 512, 163840>>>();
    pass_ab<<<2 * GRID1, 512, 229376>>>(d2b);
    pass_c<<<GRID1, 512, 229376>>>(g1b);
    pass_d<<<GRID1, 512, 229376>>>(g2b);
    outproj_mma<<<2 * NQTILES, 512, 163840>>>(obias, out, ofs);
}

// round 15
// speedup vs baseline: 1.0312x; 1.0312x over previous
#include <cuda_runtime.h>
#include <cuda_fp16.h>
#include <cstdint>

#define NPTS 8192
#define KN   32
#define DIM  256
#define DOUT 512
#define NTILES 4096      // m64 tiles over M = NPTS*KN = 262144
#define NQTILES 128
#define GRID1 152

// ---------------- device scratch (allocation-free rule) ----------------
__device__ float  g_qattn[NPTS * DIM];
__device__ __half g_fq16[NPTS * DIM];
__device__ __half g_res16[NPTS * DIM];
__device__ __half g_bufA[(size_t)NPTS * KN * DIM];  // A1 (written by pass_c)
__device__ __half g_pe  [(size_t)NPTS * KN * DIM];
__device__ __half g_h   [(size_t)NPTS * KN * DIM];
__device__ __half g_vpe [(size_t)NPTS * KN * DIM];
__device__ __half g_WkB[DIM * DIM];   // -Wk, blocked
__device__ __half g_WvB[DIM * DIM];
__device__ __half g_g1B[DIM * DIM];
__device__ __half g_g2B[DIM * DIM];
__device__ __half g_d2B[DIM * 128];
__device__ __half g_WqB[DIM * DIM];
__device__ __half g_owB[DIM * DOUT];

__device__ __forceinline__ int boff(int n, int k) {
    return ((k >> 4) * 8192 + (n >> 3) * 256 + ((k >> 3) & 1) * 128 +
            (n & 7) * 16 + (k & 7) * 2) >> 1;
}
__device__ __forceinline__ int boff512(int n, int k) {
    return ((k >> 4) * 16384 + (n >> 3) * 256 + ((k >> 3) & 1) * 128 +
            (n & 7) * 16 + (k & 7) * 2) >> 1;
}

extern "C" __global__ void convert_all(const float* __restrict__ Wk,
                                       const float* __restrict__ Wv,
                                       const float* __restrict__ g1w,
                                       const float* __restrict__ g2w,
                                       const float* __restrict__ d2w,
                                       const float* __restrict__ Wq,
                                       const float* __restrict__ ow) {
    int idx = blockIdx.x * 256 + threadIdx.x;
    if (idx < 65536) {
        int k = idx >> 8, n = idx & 255;
        g_WkB[boff(n, k)] = __float2half(-Wk[k * 256 + n]);
    } else if (idx < 131072) {
        int i = idx - 65536; int k = i >> 8, n = i & 255;
        g_WvB[boff(n, k)] = __float2half(Wv[k * 256 + n]);
    } else if (idx < 196608) {
        int i = idx - 131072; int k = i >> 8, n = i & 255;
        g_g1B[boff(n, k)] = __float2half(g1w[k * 256 + n]);
    } else if (idx < 262144) {
        int i = idx - 196608; int k = i >> 8, n = i & 255;
        g_g2B[boff(n, k)] = __float2half(g2w[k * 256 + n]);
    } else if (idx < 294912) {
        int i = idx - 262144; int k = i >> 8, n = i & 255;
        g_d2B[boff(n, k)] = __float2half(d2w[k * 256 + n]);
    } else if (idx < 360448) {
        int i = idx - 294912; int k = i >> 8, n = i & 255;
        g_WqB[boff(n, k)] = __float2half(Wq[k * 256 + n]);
    } else if (idx < 491520) {
        int i = idx - 360448; int k = i >> 9, n = i & 511;
        g_owB[boff512(n, k)] = __float2half(ow[k * 512 + n]);
    }
}

// fp32 -> fp16 conversion: feats_q -> g_fq16 (small; F conversion is fused into pass_ab)
extern "C" __global__ void __launch_bounds__(256)
convert_q(const float* __restrict__ feats_q) {
    size_t idx = (size_t)blockIdx.x * 256 + threadIdx.x;
    size_t e = idx * 2;
    const float4* src = (const float4*)feats_q;
    float4 a = __ldg(src + e), b = __ldg(src + e + 1);
    __half2 h0 = __floats2half2_rn(a.x, a.y), h1 = __floats2half2_rn(a.z, a.w);
    __half2 h2 = __floats2half2_rn(b.x, b.y), h3 = __floats2half2_rn(b.z, b.w);
    uint4 u = make_uint4(*(unsigned int*)&h0, *(unsigned int*)&h1,
                         *(unsigned int*)&h2, *(unsigned int*)&h3);
    *(uint4*)(g_fq16 + e * 4) = u;
}

extern "C" __global__ void copy_xyz_kernel(const float* __restrict__ src,
                                           float* __restrict__ dst, int n) {
    int i = blockIdx.x * blockDim.x + threadIdx.x;
    if (i < n) dst[i] = src[i];
}

// =======================================================================
__device__ __forceinline__ unsigned int swz(unsigned int row, unsigned int cb,
                                            unsigned int rb) {
    return row * rb + (cb ^ ((row & 7u) << 4));
}
__device__ __forceinline__ void cp_async16(unsigned int dst, const void* src) {
    asm volatile("cp.async.cg.shared.global [%0], [%1], 16;\n" :: "r"(dst), "l"(src) : "memory");
}
#define CP_COMMIT() asm volatile("cp.async.commit_group;\n" ::: "memory")
#define CP_WAIT(n)  asm volatile("cp.async.wait_group %0;\n" :: "n"(n) : "memory")

__device__ __forceinline__ void stage_tile(unsigned int dstb,
                                           const __half* __restrict__ src,
                                           size_t row0, int tid) {
#pragma unroll
    for (int i = 0; i < 4; ++i) {
        int c = tid + i * 512;
        unsigned int row = (unsigned int)(c >> 5);
        unsigned int c16 = (unsigned int)(c & 31) * 16u;
        cp_async16(dstb + swz(row, c16, 512u),
                   (const char*)(src + (row0 + row) * 256) + c16);
    }
}

// register-staged fp32 tile load (8 float4 / thread)
__device__ __forceinline__ void ldg_f32tile(float4 (&va)[4][2],
                                            const float* __restrict__ src,
                                            size_t row0, int tid) {
#pragma unroll
    for (int i = 0; i < 4; ++i) {
        int c = tid + i * 512;
        int row = c >> 5;
        int ce  = (c & 31) * 2;
        const float4* p = (const float4*)src + (row0 + (size_t)row) * 64 + ce;
        va[i][0] = __ldg(p);
        va[i][1] = __ldg(p + 1);
    }
}
// convert + store to swizzled fp16 smem buffer (bufoff = GENERIC byte offset)
__device__ __forceinline__ void sts_f16tile(float4 (&va)[4][2], char* smem,
                                            unsigned int bufoff, int tid) {
#pragma unroll
    for (int i = 0; i < 4; ++i) {
        int c = tid + i * 512;
        unsigned int row = (unsigned int)(c >> 5);
        unsigned int c16 = (unsigned int)(c & 31) * 16u;
        __half2 h0 = __floats2half2_rn(va[i][0].x, va[i][0].y);
        __half2 h1 = __floats2half2_rn(va[i][0].z, va[i][0].w);
        __half2 h2 = __floats2half2_rn(va[i][1].x, va[i][1].y);
        __half2 h3 = __floats2half2_rn(va[i][1].z, va[i][1].w);
        uint4 u = make_uint4(*(unsigned int*)&h0, *(unsigned int*)&h1,
                             *(unsigned int*)&h2, *(unsigned int*)&h3);
        *(uint4*)(smem + bufoff + swz(row, c16, 512u)) = u;
    }
}

template <int NSTEPS>
__device__ __forceinline__ void compute_tile(float (&acc)[2][4][4],
                                             unsigned int Abase, unsigned int arb,
                                             unsigned int Wbase, unsigned int kss,
                                             int lane, int wm, int wnl) {
    const int lr  = (lane & 7) + ((lane >> 3) & 1) * 8;
    const int lcb = ((lane >> 4) & 1) * 16;
    const int ntp = (lane >> 4) & 1;
    const int kh  = (lane >> 3) & 1;
    const int rr  = lane & 7;
#pragma unroll 4
    for (int ks = 0; ks < NSTEPS; ++ks) {
        unsigned int bf[2][4];
#pragma unroll
        for (int bg = 0; bg < 2; ++bg) {
            unsigned int ba = Wbase + (unsigned int)ks * kss
                            + (unsigned int)((wnl * 4 + bg * 2 + ntp) * 256 + kh * 128 + rr * 16);
            asm volatile("ldmatrix.sync.aligned.m8n8.x4.shared.b16 {%0,%1,%2,%3}, [%4];\n"
                         : "=r"(bf[bg][0]), "=r"(bf[bg][1]), "=r"(bf[bg][2]), "=r"(bf[bg][3])
                         : "r"(ba));
        }
#pragma unroll
        for (int mt = 0; mt < 2; ++mt) {
            unsigned int a0, a1, a2, a3;
            unsigned int ad = Abase + swz((unsigned int)(wm * 32 + mt * 16 + lr),
                                          (unsigned int)(ks * 32 + lcb), arb);
            asm volatile("ldmatrix.sync.aligned.m8n8.x4.shared.b16 {%0,%1,%2,%3}, [%4];\n"
                         : "=r"(a0), "=r"(a1), "=r"(a2), "=r"(a3) : "r"(ad));
#pragma unroll
            for (int nt = 0; nt < 4; ++nt) {
                asm volatile(
                    "mma.sync.aligned.m16n8k16.row.col.f32.f16.f16.f32 "
                    "{%0,%1,%2,%3},{%4,%5,%6,%7},{%8,%9},{%0,%1,%2,%3};\n"
                    : "+f"(acc[mt][nt][0]), "+f"(acc[mt][nt][1]),
                      "+f"(acc[mt][nt][2]), "+f"(acc[mt][nt][3])
                    : "r"(a0), "r"(a1), "r"(a2), "r"(a3),
                      "r"(bf[nt >> 1][(nt & 1) * 2]), "r"(bf[nt >> 1][(nt & 1) * 2 + 1]));
            }
        }
    }
}

#define ZERO_ACC(acc) \
    _Pragma("unroll") for (int _m = 0; _m < 2; ++_m) { \
    _Pragma("unroll") for (int _n = 0; _n < 4; ++_n) { \
    _Pragma("unroll") for (int _i = 0; _i < 4; ++_i) { acc[_m][_n][_i] = 0.f; } } }

// =======================================================================
// pe kernel: per point (m32), H1 in smem, pe = H1@d2. d2 resident.
// =======================================================================
extern "C" __global__ void __launch_bounds__(256, 2)
pe_kernel(const float* __restrict__ xyz_q, const float* __restrict__ xyz_kv,
          const float* __restrict__ d1w, const float* __restrict__ d1b) {
    extern __shared__ char smem[];
    const unsigned int smb = (unsigned int)__cvta_generic_to_shared(smem);
    const int tid  = threadIdx.x;
    const int lane = tid & 31;
    const int wnl  = tid >> 5;
    const int g    = lane >> 2, tig = lane & 3;

    for (int i = tid; i < 4096; i += 256) {
        cp_async16(smb + (unsigned int)(i * 16), (const char*)g_d2B + i * 16);
    }
    CP_COMMIT(); CP_WAIT(0);
    __syncthreads();

    const unsigned int H1 = smb + 65536u;
    for (int pt = blockIdx.x; pt < NPTS; pt += 2 * GRID1) {
        __syncthreads();
        {
            unsigned int row = (unsigned int)(tid >> 3);
            int cb = (tid & 7) * 16;
            float qx = __ldg(xyz_q + pt * 3 + 0);
            float qy = __ldg(xyz_q + pt * 3 + 1);
            float qz = __ldg(xyz_q + pt * 3 + 2);
            const float* pk = xyz_kv + ((size_t)pt * KN + row) * 3;
            float rx = qx - __ldg(pk + 0), ry = qy - __ldg(pk + 1), rz = qz - __ldg(pk + 2);
#pragma unroll 4
            for (int c = cb; c < cb + 16; c += 2) {
                float h0 = fmaf(rx, __ldg(d1w + c),     fmaf(ry, __ldg(d1w + 128 + c),     fmaf(rz, __ldg(d1w + 256 + c),     __ldg(d1b + c))));
                float h1 = fmaf(rx, __ldg(d1w + c + 1), fmaf(ry, __ldg(d1w + 128 + c + 1), fmaf(rz, __ldg(d1w + 256 + c + 1), __ldg(d1b + c + 1))));
                __half2 hh = __floats2half2_rn(fmaxf(h0, 0.f), fmaxf(h1, 0.f));
                *(__half2*)(smem + 65536 + swz(row, (unsigned int)c * 2u, 256u)) = hh;
            }
        }
        __syncthreads();
        float acc[2][4][4];
        ZERO_ACC(acc);
        compute_tile<8>(acc, H1, 256u, smb, 8192u, lane, 0, wnl);
#pragma unroll
        for (int nt = 0; nt < 4; ++nt) {
            int c = wnl * 32 + nt * 8 + 2 * tig;
#pragma unroll
            for (int mt = 0; mt < 2; ++mt) {
                size_t r0 = (size_t)pt * 32 + mt * 16 + g;
                __half2 lo = __floats2half2_rn(acc[mt][nt][0], acc[mt][nt][1]);
                __half2 hi = __floats2half2_rn(acc[mt][nt][2], acc[mt][nt][3]);
                *(__half2*)(g_pe + r0 * 256 + c)       = lo;
                *(__half2*)(g_pe + (r0 + 8) * 256 + c) = hi;
            }
        }
    }
}

// =======================================================================
extern "C" __global__ void __launch_bounds__(512, 1)
qproj_mma() {
    extern __shared__ char smem[];
    const unsigned int smb = (unsigned int)__cvta_generic_to_shared(smem);
    const int tid  = threadIdx.x;
    const int lane = tid & 31;
    const int wid  = tid >> 5;
    const int wm   = (wid >> 3) & 1, wnl = wid & 7;
    const int g    = lane >> 2, tig = lane & 3;
    const int t    = blockIdx.x;

    for (int i = tid; i < 8192; i += 512) {
        cp_async16(smb + (unsigned int)(i * 16), (const char*)g_WqB + i * 16);
    }
    stage_tile(smb + 131072u, g_fq16, (size_t)t * 64, tid);
    CP_COMMIT(); CP_WAIT(0);
    __syncthreads();

    float acc[2][4][4];
    ZERO_ACC(acc);
    compute_tile<16>(acc, smb + 131072u, 512u, smb, 8192u, lane, wm, wnl);
#pragma unroll
    for (int nt = 0; nt < 4; ++nt) {
        int c = wnl * 32 + nt * 8 + 2 * tig;
#pragma unroll
        for (int mt = 0; mt < 2; ++mt) {
            size_t r0 = (size_t)t * 64 + wm * 32 + mt * 16 + g;
            g_qattn[r0 * 256 + c]           = acc[mt][nt][0];
            g_qattn[r0 * 256 + c + 1]       = acc[mt][nt][1];
            g_qattn[(r0 + 8) * 256 + c]     = acc[mt][nt][2];
            g_qattn[(r0 + 8) * 256 + c + 1] = acc[mt][nt][3];
        }
    }
}

extern "C" __global__ void __launch_bounds__(512, 1)
outproj_mma(const float* __restrict__ ob, float* __restrict__ out, long long ofs) {
    extern __shared__ char smem[];
    const unsigned int smb = (unsigned int)__cvta_generic_to_shared(smem);
    const int tid  = threadIdx.x;
    const int lane = tid & 31;
    const int wid  = tid >> 5;
    const int wm   = (wid >> 3) & 1, wnl = wid & 7;
    const int g    = lane >> 2, tig = lane & 3;
    const int t    = blockIdx.x >> 1;
    const int nh   = blockIdx.x & 1;

    for (int i = tid; i < 8192; i += 512) {
        int kb = i >> 9, rem = i & 511;
        cp_async16(smb + (unsigned int)(kb * 8192 + rem * 16),
                   (const char*)g_owB + kb * 16384 + nh * 8192 + rem * 16);
    }
    stage_tile(smb + 131072u, g_res16, (size_t)t * 64, tid);
    CP_COMMIT(); CP_WAIT(0);
    __syncthreads();

    float acc[2][4][4];
    ZERO_ACC(acc);
    compute_tile<16>(acc, smb + 131072u, 512u, smb, 8192u, lane, wm, wnl);
    float* dst = out + ofs;
#pragma unroll
    for (int nt = 0; nt < 4; ++nt) {
        int c = nh * 256 + wnl * 32 + nt * 8 + 2 * tig;
        float b0 = __ldg(ob + c), b1 = __ldg(ob + c + 1);
#pragma unroll
        for (int mt = 0; mt < 2; ++mt) {
            size_t r0 = (size_t)t * 64 + wm * 32 + mt * 16 + g;
            dst[r0 * 512 + c]           = acc[mt][nt][0] + b0;
            dst[r0 * 512 + c + 1]       = acc[mt][nt][1] + b1;
            dst[(r0 + 8) * 512 + c]     = acc[mt][nt][2] + b0;
            dst[(r0 + 8) * 512 + c + 1] = acc[mt][nt][3] + b1;
        }
    }
}

// =======================================================================
// AB: h = q + d2b + pe + F@(-Wk) ; vpe = d2b + pe + F@Wv
// F read DIRECTLY from fp32 feats_kv via register-staged LDG->cvt->STS
// (2-deep smem buffers); Wk/Wv n-halves resident via cp.async.
// =======================================================================
extern "C" __global__ void __launch_bounds__(512, 1)
pass_ab(const float* __restrict__ feats_kv, const float* __restrict__ d2b) {
    extern __shared__ char smem[];
    const unsigned int smb = (unsigned int)__cvta_generic_to_shared(smem);
    const int tid  = threadIdx.x;
    const int lane = tid & 31;
    const int wid  = tid >> 5;
    const int b    = blockIdx.x;
    const int nh   = b & 1;
    const int out  = wid >> 3;
    const int w8   = wid & 7;
    const int wm   = w8 >> 2, wnl = w8 & 3;
    const int g    = lane >> 2, tig = lane & 3;
    const unsigned int Wbase = smb + (unsigned int)out * 65536u;
    const unsigned int DB = smb + 131072u;   // shared-window address for ldmatrix
    const unsigned int DBG = 131072u;        // generic byte offset for STS

    // weights: Wk/Wv n-halves (2 x 64KB)
    for (int i = tid; i < 8192; i += 512) {
        int w = i >> 12, c = i & 4095, ks = c >> 8, rem = c & 255;
        const char* srcb = (const char*)(w ? g_WvB : g_WkB) + ks * 8192 + nh * 4096 + rem * 16;
        cp_async16(smb + (unsigned int)(w * 65536 + ks * 4096 + rem * 16), srcb);
    }
    CP_COMMIT();

    const int t0 = b >> 1;
    float4 va[4][2];
    ldg_f32tile(va, feats_kv, (size_t)t0 * 64, tid);
    CP_WAIT(0);
    __syncthreads();                         // weights visible
    sts_f16tile(va, smem, DBG, tid);         // buf0 = tile t0
    if (t0 + GRID1 < NTILES) {
        ldg_f32tile(va, feats_kv, (size_t)(t0 + GRID1) * 64, tid);
    }
    __syncthreads();                         // buf0 visible

    int cc[4]; float bb0[4], bb1[4];
#pragma unroll
    for (int nt = 0; nt < 4; ++nt) {
        cc[nt]  = nh * 128 + wnl * 32 + nt * 8 + 2 * tig;
        bb0[nt] = __ldg(d2b + cc[nt]);
        bb1[nt] = __ldg(d2b + cc[nt] + 1);
    }

    int it = 0;
    for (int t = t0; t < NTILES; t += GRID1, ++it) {
        // STS tile t+1 (loaded last iteration) into the other buffer
        if (t + GRID1 < NTILES) {
            sts_f16tile(va, smem, DBG + (unsigned int)((it + 1) & 1) * 32768u, tid);
        }
        // LDG tile t+2 (latency hidden under the mma stream)
        if (t + 2 * GRID1 < NTILES) {
            ldg_f32tile(va, feats_kv, (size_t)(t + 2 * GRID1) * 64, tid);
        }
        // epilogue operand prefetch
        unsigned int peP[4][4];
        float a0[4], a1[4];
        {
            const float* qrow = g_qattn + (size_t)(t * 2 + wm) * DIM;
            const size_t rbase = (size_t)t * 64 + wm * 32;
#pragma unroll
            for (int nt = 0; nt < 4; ++nt) {
                int c = cc[nt];
                a0[nt] = bb0[nt]; a1[nt] = bb1[nt];
                if (out == 0) { a0[nt] += __ldg(qrow + c); a1[nt] += __ldg(qrow + c + 1); }
#pragma unroll
                for (int mt = 0; mt < 2; ++mt) {
                    size_t r0 = rbase + mt * 16 + g;
                    peP[nt][mt * 2]     = __ldg((const unsigned int*)(g_pe + r0 * 256 + c));
                    peP[nt][mt * 2 + 1] = __ldg((const unsigned int*)(g_pe + (r0 + 8) * 256 + c));
                }
            }
        }

        float acc[2][4][4];
        ZERO_ACC(acc);
        compute_tile<16>(acc, DB + (unsigned int)(it & 1) * 32768u, 512u, Wbase, 4096u, lane, wm, wnl);

        __half* dstArr = out ? g_vpe : g_h;
#pragma unroll
        for (int nt = 0; nt < 4; ++nt) {
            int c = cc[nt];
#pragma unroll
            for (int mt = 0; mt < 2; ++mt) {
                size_t r0 = (size_t)t * 64 + wm * 32 + mt * 16 + g;
                float2 pl = __half22float2(*(__half2*)&peP[nt][mt * 2]);
                float2 ph = __half22float2(*(__half2*)&peP[nt][mt * 2 + 1]);
                __half2 lo = __floats2half2_rn(acc[mt][nt][0] + a0[nt] + pl.x,
                                               acc[mt][nt][1] + a1[nt] + pl.y);
                __half2 hi = __floats2half2_rn(acc[mt][nt][2] + a0[nt] + ph.x,
                                               acc[mt][nt][3] + a1[nt] + ph.y);
                *(__half2*)(dstArr + r0 * 256 + c)       = lo;
                *(__half2*)(dstArr + (r0 + 8) * 256 + c) = hi;
            }
        }
        __syncthreads();   // compute of buf[it&1] done; next iter may STS into it
    }
}

// =======================================================================
// C: A1 = relu(h @ g1 + g1b) -> g_bufA. g1 resident. grid 152.
// =======================================================================
extern "C" __global__ void __launch_bounds__(512, 1)
pass_c(const float* __restrict__ g1b) {
    extern __shared__ char smem[];
    const unsigned int smb = (unsigned int)__cvta_generic_to_shared(smem);
    const int tid  = threadIdx.x;
    const int lane = tid & 31;
    const int wid  = tid >> 5;
    const int wm   = (wid >> 3) & 1, wnl = wid & 7;
    const int g    = lane >> 2, tig = lane & 3;
    const unsigned int DB = smb + 131072u;

    for (int i = tid; i < 8192; i += 512) {
        cp_async16(smb + (unsigned int)(i * 16), (const char*)g_g1B + i * 16);
    }
    const int t0 = blockIdx.x;
    stage_tile(DB, g_h, (size_t)t0 * 64, tid);
    CP_COMMIT();
    if (t0 + GRID1 < NTILES) {
        stage_tile(DB + 32768u, g_h, (size_t)(t0 + GRID1) * 64, tid);
        CP_COMMIT();
    }

    int cc[4]; float bb0[4], bb1[4];
#pragma unroll
    for (int nt = 0; nt < 4; ++nt) {
        cc[nt]  = wnl * 32 + nt * 8 + 2 * tig;
        bb0[nt] = __ldg(g1b + cc[nt]);
        bb1[nt] = __ldg(g1b + cc[nt] + 1);
    }

    int it = 0;
    for (int t = t0; t < NTILES; t += GRID1, ++it) {
        if (t + GRID1 < NTILES) { CP_WAIT(1); } else { CP_WAIT(0); }
        __syncthreads();
        int t2 = t + 2 * GRID1;
        if (t2 < NTILES) {
            stage_tile(DB + (unsigned int)((it + 2) % 3) * 32768u, g_h, (size_t)t2 * 64, tid);
            CP_COMMIT();
        }
        float acc[2][4][4];
        ZERO_ACC(acc);
        compute_tile<16>(acc, DB + (unsigned int)(it % 3) * 32768u, 512u, smb, 8192u, lane, wm, wnl);
#pragma unroll
        for (int nt = 0; nt < 4; ++nt) {
            int c = cc[nt];
#pragma unroll
            for (int mt = 0; mt < 2; ++mt) {
                size_t r0 = (size_t)t * 64 + wm * 32 + mt * 16 + g;
                __half2 lo = __floats2half2_rn(fmaxf(acc[mt][nt][0] + bb0[nt], 0.f),
                                               fmaxf(acc[mt][nt][1] + bb1[nt], 0.f));
                __half2 hi = __floats2half2_rn(fmaxf(acc[mt][nt][2] + bb0[nt], 0.f),
                                               fmaxf(acc[mt][nt][3] + bb1[nt], 0.f));
                *(__half2*)(g_bufA + r0 * 256 + c)       = lo;
                *(__half2*)(g_bufA + (r0 + 8) * 256 + c) = hi;
            }
        }
    }
}

// =======================================================================
// D: logits = A1 @ g2 + g2b; softmax over 32 neighbors; res -> g_res16.
// =======================================================================
extern "C" __global__ void __launch_bounds__(512, 1)
pass_d(const float* __restrict__ g2b) {
    extern __shared__ char smem[];
    const unsigned int smb = (unsigned int)__cvta_generic_to_shared(smem);
    const int tid  = threadIdx.x;
    const int lane = tid & 31;
    const int wid  = tid >> 5;
    const int wm   = (wid >> 3) & 1, wnl = wid & 7;
    const int g    = lane >> 2, tig = lane & 3;
    const unsigned int DB = smb + 131072u;

    for (int i = tid; i < 8192; i += 512) {
        cp_async16(smb + (unsigned int)(i * 16), (const char*)g_g2B + i * 16);
    }
    const int t0 = blockIdx.x;
    stage_tile(DB, g_bufA, (size_t)t0 * 64, tid);
    CP_COMMIT();
    if (t0 + GRID1 < NTILES) {
        stage_tile(DB + 32768u, g_bufA, (size_t)(t0 + GRID1) * 64, tid);
        CP_COMMIT();
    }

    int cc[4]; float bb0[4], bb1[4];
#pragma unroll
    for (int nt = 0; nt < 4; ++nt) {
        cc[nt]  = wnl * 32 + nt * 8 + 2 * tig;
        bb0[nt] = __ldg(g2b + cc[nt]);
        bb1[nt] = __ldg(g2b + cc[nt] + 1);
    }

    int it = 0;
    for (int t = t0; t < NTILES; t += GRID1, ++it) {
        if (t + GRID1 < NTILES) { CP_WAIT(1); } else { CP_WAIT(0); }
        __syncthreads();
        int t2 = t + 2 * GRID1;
        if (t2 < NTILES) {
            stage_tile(DB + (unsigned int)((it + 2) % 3) * 32768u, g_bufA, (size_t)t2 * 64, tid);
            CP_COMMIT();
        }
        unsigned int vP[4][4];
        {
            const size_t rb = (size_t)t * 64 + wm * 32;
#pragma unroll
            for (int nt = 0; nt < 4; ++nt) {
                int c = cc[nt];
                vP[nt][0] = __ldg((const unsigned int*)(g_vpe + (rb + g) * 256 + c));
                vP[nt][1] = __ldg((const unsigned int*)(g_vpe + (rb + 8 + g) * 256 + c));
                vP[nt][2] = __ldg((const unsigned int*)(g_vpe + (rb + 16 + g) * 256 + c));
                vP[nt][3] = __ldg((const unsigned int*)(g_vpe + (rb + 24 + g) * 256 + c));
            }
        }

        float acc[2][4][4];
        ZERO_ACC(acc);
        compute_tile<16>(acc, DB + (unsigned int)(it % 3) * 32768u, 512u, smb, 8192u, lane, wm, wnl);

#pragma unroll
        for (int nt = 0; nt < 4; ++nt) {
            int c = cc[nt];
            float2 v00 = __half22float2(*(__half2*)&vP[nt][0]);
            float2 v01 = __half22float2(*(__half2*)&vP[nt][1]);
            float2 v10 = __half22float2(*(__half2*)&vP[nt][2]);
            float2 v11 = __half22float2(*(__half2*)&vP[nt][3]);
#pragma unroll
            for (int ci = 0; ci < 2; ++ci) {
                float gb = ci ? bb1[nt] : bb0[nt];
                float l0 = acc[0][nt][ci]     + gb;
                float l1 = acc[0][nt][ci + 2] + gb;
                float l2 = acc[1][nt][ci]     + gb;
                float l3 = acc[1][nt][ci + 2] + gb;
                float v0 = ci ? v00.y : v00.x;
                float v1 = ci ? v01.y : v01.x;
                float v2 = ci ? v10.y : v10.x;
                float v3 = ci ? v11.y : v11.x;
                float mx = fmaxf(fmaxf(l0, l1), fmaxf(l2, l3));
                mx = fmaxf(mx, __shfl_xor_sync(0xffffffffu, mx, 4));
                mx = fmaxf(mx, __shfl_xor_sync(0xffffffffu, mx, 8));
                mx = fmaxf(mx, __shfl_xor_sync(0xffffffffu, mx, 16));
                float e0 = __expf(l0 - mx), e1 = __expf(l1 - mx);
                float e2 = __expf(l2 - mx), e3 = __expf(l3 - mx);
                float ss = (e0 + e1) + (e2 + e3);
                float ws = (e0 * v0 + e1 * v1) + (e2 * v2 + e3 * v3);
                ss += __shfl_xor_sync(0xffffffffu, ss, 4);
                ws += __shfl_xor_sync(0xffffffffu, ws, 4);
                ss += __shfl_xor_sync(0xffffffffu, ss, 8);
                ws += __shfl_xor_sync(0xffffffffu, ws, 8);
                ss += __shfl_xor_sync(0xffffffffu, ss, 16);
                ws += __shfl_xor_sync(0xffffffffu, ws, 16);
                if (g == 0) {
                    g_res16[(size_t)(t * 2 + wm) * DIM + c + ci] = __float2half(ws / ss);
                }
            }
        }
    }
}

// =======================================================================
extern "C" void kernel_launch(void* const* d_in, const int* in_sizes, int n_in,
                              void* d_out, int out_size) {
    const float* xyz_q    = (const float*)d_in[0];
    const float* feats_q  = (const float*)d_in[1];
    const float* xyz_kv   = (const float*)d_in[2];
    const float* feats_kv = (const float*)d_in[3];
    const float* Wq       = (const float*)d_in[4];
    const float* Wk       = (const float*)d_in[5];
    const float* Wv       = (const float*)d_in[6];
    const float* d1w      = (const float*)d_in[7];
    const float* d1b      = (const float*)d_in[8];
    const float* d2w      = (const float*)d_in[9];
    const float* d2b      = (const float*)d_in[10];
    const float* g1w      = (const float*)d_in[11];
    const float* g1b      = (const float*)d_in[12];
    const float* g2w      = (const float*)d_in[13];
    const float* g2b      = (const float*)d_in[14];
    const float* ow       = (const float*)d_in[15];
    const float* obias    = (const float*)d_in[16];
    float* out = (float*)d_out;

    long long ofs = (long long)out_size - (long long)NPTS * DOUT;
    if (ofs < 0) ofs = 0;
    if (ofs > 0)
        copy_xyz_kernel<<<(int)((ofs + 255) / 256), 256>>>(xyz_q, out, (int)ofs);

    convert_all<<<1920, 256>>>(Wk, Wv, g1w, g2w, d2w, Wq, ow);
    convert_q<<<(NPTS * DIM / 8 + 255) / 256, 256>>>(feats_q);

    cudaFuncSetAttribute(pe_kernel,   cudaFuncAttributeMaxDynamicSharedMemorySize, 73728);
    cudaFuncSetAttribute(qproj_mma,   cudaFuncAttributeMaxDynamicSharedMemorySize, 163840);
    cudaFuncSetAttribute(outproj_mma, cudaFuncAttributeMaxDynamicSharedMemorySize, 163840);
    cudaFuncSetAttribute(pass_ab, cudaFuncAttributeMaxDynamicSharedMemorySize, 196608);
    cudaFuncSetAttribute(pass_c,  cudaFuncAttributeMaxDynamicSharedMemorySize, 229376);
    cudaFuncSetAttribute(pass_d,  cudaFuncAttributeMaxDynamicSharedMemorySize, 229376);

    qproj_mma<<<NQTILES, 512, 163840>>>();
    pe_kernel<<<2 * GRID1, 256, 73728>>>(xyz_q, xyz_kv, d1w, d1b);
    pass_ab<<<2 * GRID1, 512, 196608>>>(feats_kv, d2b);
    pass_c<<<GRID1, 512, 229376>>>(g1b);
    pass_d<<<GRID1, 512, 229376>>>(g2b);
    outproj_mma<<<2 * NQTILES, 512, 163840>>>(obias, out, ofs);
}